// round 15
// baseline (speedup 1.0000x reference)
#include <cuda_runtime.h>

#define NC    91
#define CM1   90
#define BIMG  8
#define DET   100
#define NBINS 4096
#define CAP   4096
#define MAXP  4096
#define MAXN  (BIMG*MAXP)
#define BPI   18                 // blocks per image
#define NBLK  (BIMG*BPI)         // 144
#define NTHR  1024
#define NWRP  (NTHR/32)
#define QPB   (NTHR/8)           // quarter-warps per block = 128
#define QPI   (BPI*QPB)          // 2304 quarter-warps per image
#define DBINS 2048
#define CAPL  512
#define RCAP  2048

// ---------- scratch (static device globals, zero-initialized) ----------
__device__ unsigned long long g_rowinfo[MAXN];   // k1<<32 | (k2&~127)|cls
__device__ float    g_keyoff[MAXN];
__device__ unsigned g_hist[BIMG][NBINS];
__device__ int      g_selp[BIMG][DET];
__device__ unsigned g_adone[BIMG];
__device__ unsigned g_dflag[BIMG];
__device__ unsigned g_edone[BIMG];

__device__ __forceinline__ unsigned f2sort(float x) {
    unsigned u = __float_as_uint(x);
    return (u & 0x80000000u) ? ~u : (u | 0x80000000u);
}
__device__ __forceinline__ void wait_ge(volatile unsigned* p, unsigned v) {
    while (*p < v) __nanosleep(32);
}

__device__ __forceinline__ void bitonic(unsigned long long* a, int m, int tid) {
    for (int k = 2; k <= m; k <<= 1)
        for (int j = k >> 1; j > 0; j >>= 1) {
            for (int i = tid; i < m; i += NTHR) {
                int ixj = i ^ j;
                if (ixj > i) {
                    unsigned long long x = a[i], y = a[ixj];
                    bool up = ((i & k) == 0);
                    if ((x > y) == up) { a[i] = y; a[ixj] = x; }
                }
            }
            __syncthreads();
        }
}

__global__ void __launch_bounds__(NTHR, 1)
fused_rcnn(const float* __restrict__ lg,
           const float* __restrict__ reg,
           const float* __restrict__ props,
           const float* __restrict__ ft,
           float* __restrict__ out_boxes,
           float* __restrict__ out_feats,
           int P, int FD) {
    __shared__ __align__(16) unsigned long long s_sort[CAP];  // 32 KB
    __shared__ __align__(16) unsigned s_u[DBINS];             // 8 KB: rescan list / hist / list
    __shared__ unsigned s_TU;
    __shared__ int s_cutB, s_lcnt, s_n, s_nr;

    const int tid  = threadIdx.x;
    const int bid  = blockIdx.x;
    const int wid  = tid >> 5;
    const int lane = tid & 31;
    const int img  = bid / BPI;
    const int j    = bid - img * BPI;
    const long ib  = (long)img * P;
    const bool has2 = lane < (NC - 64);
    const float NEG = __int_as_float(0xff800000);  // -inf

    // ===== Phase A: quarter-warp-per-row stats (sum + max/argmax/2nd-max) =====
    {
        const int qw = j * QPB + (tid >> 3);     // quarter-warp index within image
        const int ql = tid & 7;

        for (int r = qw; r < P; r += QPI) {
            const float* rp = lg + (ib + r) * NC;
            float s = 0.f, va = NEG, vb = NEG;
            unsigned ca = 0u;
            #pragma unroll
            for (int k = 0; k < 12; k++) {
                int c = ql + (k << 3);
                if (c < NC) {
                    float v = rp[c];
                    s += __expf(v);
                    float vv = (c == 0) ? NEG : v;   // exclude background class
                    if (vv > va) { vb = va; va = vv; ca = (unsigned)c; }
                    else         { vb = fmaxf(vb, vv); }
                }
            }
            // 3-step tree within the 8-lane group: sum + (max,cls,2nd) triple merge
            #pragma unroll
            for (int o = 1; o < 8; o <<= 1) {
                float    os  = __shfl_xor_sync(~0u, s,  o, 8);
                float    ova = __shfl_xor_sync(~0u, va, o, 8);
                unsigned oca = __shfl_xor_sync(~0u, ca, o, 8);
                float    ovb = __shfl_xor_sync(~0u, vb, o, 8);
                s += os;
                if (ova > va)       { vb = fmaxf(va, ovb); va = ova; ca = oca; }
                else if (ova == va) { vb = va; ca = min(ca, oca); }
                else                { vb = fmaxf(vb, ova); }
            }
            if (ql == 0) {
                float ko = __logf(s);
                unsigned k1 = f2sort(va - ko);
                unsigned lo = (f2sort(vb - ko) & ~127u) | ca;
                long row = ib + r;
                g_rowinfo[row] = ((unsigned long long)k1 << 32) | lo;
                g_keyoff[row]  = ko;
                atomicAdd(&g_hist[img][k1 >> 20], 1u);
            }
        }
        __threadfence();
        __syncthreads();
        if (tid == 0) atomicAdd(&g_adone[img], 1u);
        if (j >= 4) return;
    }

    // ========== Phase D: select + rank + decode (block j==0 only) ==========
    if (j == 0) {
        if (tid == 0) wait_ge(&g_adone[img], BPI);
        __syncthreads();
        __threadfence();

        // --- TU: rank-100 coarse threshold from histogram (warp 0) ---
        if (wid == 0) {
            const unsigned* hb = g_hist[img];
            unsigned part = 0;
            #pragma unroll
            for (int k = 0; k < 64; k++) part += hb[(lane << 6) + k];
            unsigned sfx = part;
            #pragma unroll
            for (int o = 1; o < 32; o <<= 1) {
                unsigned t = __shfl_down_sync(~0u, sfx, o);
                if (lane + o < 32) sfx += t;
            }
            unsigned bal = __ballot_sync(~0u, sfx >= DET);
            int lstar = 31 - __clz(bal);
            unsigned nxt = __shfl_sync(~0u, sfx, (lstar + 1) & 31);
            unsigned above = (lstar < 31) ? nxt : 0u;
            int base = lstar << 6;
            unsigned tu = 0, run = above;
            #pragma unroll
            for (int h = 1; h >= 0; h--) {
                unsigned v = hb[base + (h << 5) + lane];
                unsigned s2 = v;
                #pragma unroll
                for (int o = 1; o < 32; o <<= 1) {
                    unsigned t = __shfl_down_sync(~0u, s2, o);
                    if (lane + o < 32) s2 += t;
                }
                unsigned tot = __shfl_sync(~0u, s2, 0);
                if (run + tot >= DET) {
                    unsigned b2 = __ballot_sync(~0u, run + s2 >= DET);
                    int l2 = 31 - __clz(b2);
                    tu = ((unsigned)(base + (h << 5) + l2)) << 20;
                    break;
                }
                run += tot;
            }
            if (lane == 0) s_TU = tu;
        }
        if (tid == 0) { s_n = 0; s_nr = 0; }
        __syncthreads();
        const unsigned TU = s_TU;
        const float Tf = __uint_as_float(~TU);   // sort2f(TU): keys strictly negative

        // --- scan rows: fast-push max-class candidates, queue rare rescans ---
        for (int r = tid; r < P; r += NTHR) {
            unsigned long long u = g_rowinfo[ib + r];
            unsigned k1 = (unsigned)(u >> 32);
            if (k1 >= TU) {
                unsigned lo = (unsigned)u;
                if (lo >= TU) {                       // second class may also qualify
                    int q = atomicAdd(&s_nr, 1);
                    if (q < RCAP) ((int*)s_u)[q] = r;
                } else {
                    unsigned cls = lo & 127u;
                    int q = atomicAdd(&s_n, 1);
                    if (q < CAP)
                        s_sort[q] = ((unsigned long long)(~k1) << 32)
                                    | (unsigned)(r * CM1 + (int)cls - 1);
                }
            }
        }
        __syncthreads();

        // --- rescan rows with >=2 qualifying classes (warp per row) ---
        {
            int nr = min(s_nr, RCAP);
            for (int i = wid; i < nr; i += NWRP) {
                int r = ((int*)s_u)[i];
                float ko = g_keyoff[ib + r];
                const float* rp = lg + (ib + r) * NC;
                float v0 = rp[lane], v1 = rp[lane + 32];
                float v2 = has2 ? rp[lane + 64] : NEG;
                float d0 = v0 - ko, d1 = v1 - ko, d2 = v2 - ko;
                if (lane >= 1 && d0 >= Tf) {
                    int q = atomicAdd(&s_n, 1);
                    if (q < CAP)
                        s_sort[q] = ((unsigned long long)(~f2sort(d0)) << 32)
                                    | (unsigned)(r * CM1 + (lane - 1));
                }
                if (d1 >= Tf) {
                    int q = atomicAdd(&s_n, 1);
                    if (q < CAP)
                        s_sort[q] = ((unsigned long long)(~f2sort(d1)) << 32)
                                    | (unsigned)(r * CM1 + (lane + 31));
                }
                if (d2 >= Tf) {
                    int q = atomicAdd(&s_n, 1);
                    if (q < CAP)
                        s_sort[q] = ((unsigned long long)(~f2sort(d2)) << 32)
                                    | (unsigned)(r * CM1 + (lane + 63));
                }
            }
        }
        __syncthreads();
        int n = min(s_n, CAP);

        // --- bucket-select to <=CAPL ---
        for (int i = tid; i < DBINS; i += NTHR) s_u[i] = 0;
        __syncthreads();
        for (int i = tid; i < n; i += NTHR)
            atomicAdd(&s_u[(unsigned)(s_sort[i] >> 53)], 1u);
        __syncthreads();
        if (wid == 0) {
            if (lane == 0) s_cutB = DBINS - 1;
            unsigned cum = 0;
            for (int bp = 0; bp < DBINS; bp += 32) {
                unsigned v = s_u[bp + lane];
                unsigned pf = v;
                #pragma unroll
                for (int o = 1; o < 32; o <<= 1) {
                    unsigned t = __shfl_up_sync(~0u, pf, o);
                    if (lane >= o) pf += t;
                }
                unsigned tot = __shfl_sync(~0u, pf, 31);
                if (cum + tot >= DET) {
                    unsigned bal = __ballot_sync(~0u, cum + pf >= DET);
                    int l = __ffs(bal) - 1;
                    if (lane == 0) s_cutB = bp + l;
                    break;
                }
                cum += tot;
            }
        }
        if (tid == 0) s_lcnt = 0;
        __syncthreads();
        unsigned cutB = (unsigned)s_cutB;
        unsigned long long* s_list = (unsigned long long*)s_u;
        for (int i = tid; i < n; i += NTHR) {
            unsigned long long key = s_sort[i];
            if ((unsigned)(key >> 53) <= cutB) {
                int pos = atomicAdd(&s_lcnt, 1);
                if (pos < CAPL) s_list[pos] = key;
            }
        }
        __syncthreads();
        int ln = s_lcnt;
        unsigned long long* res;
        if (ln <= CAPL) {
            // --- rank-select: keys unique -> exact stable top-100 (no syncs in loop) ---
            if (tid < ln) {
                unsigned long long key = s_list[tid];
                int rank = 0;
                #pragma unroll 4
                for (int k = 0; k < ln; k++) rank += (s_list[k] < key);
                if (rank < DET) s_sort[rank] = key;
            }
            __syncthreads();
            res = s_sort;
        } else {
            int m = 128; while (m < n) m <<= 1;
            for (int i = tid; i < m; i += NTHR) if (i >= n) s_sort[i] = ~0ULL;
            __syncthreads();
            bitonic(s_sort, m, tid);
            res = s_sort;
        }

        // --- decode top-100 boxes ---
        if (tid < DET) {
            unsigned idx = (unsigned)(res[tid] & 0xffffffffu);
            int p = idx / CM1;
            int c = idx % CM1 + 1;
            long gp = ib + p;
            const float* pr = props + gp * 4;
            float x1 = pr[0], y1 = pr[1], x2 = pr[2], y2 = pr[3];
            float w = x2 - x1, h = y2 - y1;
            float cx = x1 + 0.5f * w, cy = y1 + 0.5f * h;
            const float* rr = reg + gp * (4 * NC) + 4 * c;
            const float CLIP = 4.135166556742356f;  // log(1000/16)
            float dx = rr[0] / 10.0f, dy = rr[1] / 10.0f;
            float dw = fminf(rr[2] / 5.0f, CLIP);
            float dh = fminf(rr[3] / 5.0f, CLIP);
            float pcx = dx * w + cx, pcy = dy * h + cy;
            float pw = expf(dw) * w, ph = expf(dh) * h;
            float bx1 = pcx - 0.5f * pw, by1 = pcy - 0.5f * ph;
            float bx2 = pcx + 0.5f * pw, by2 = pcy + 0.5f * ph;
            bx1 = fminf(fmaxf(bx1, 0.f), 800.f);
            bx2 = fminf(fmaxf(bx2, 0.f), 800.f);
            by1 = fminf(fmaxf(by1, 0.f), 800.f);
            by2 = fminf(fmaxf(by2, 0.f), 800.f);
            float* o = out_boxes + ((long)img * DET + tid) * 4;
            o[0] = bx1 / 800.f; o[1] = by1 / 800.f;
            o[2] = bx2 / 800.f; o[3] = by2 / 800.f;
            g_selp[img][tid] = p;
        }
        __threadfence();
        __syncthreads();
        if (tid == 0) atomicExch(&g_dflag[img], 1u);
    }

    // ========== Phase E: feature gather, 25 rows per block (j=0..3) ==========
    {
        if (tid == 0 && j != 0) wait_ge(&g_dflag[img], 1u);
        __syncthreads();
        __threadfence();

        const int FD4 = FD >> 2;
        const int tot = 25 * FD4;
        const float4* fsrc = (const float4*)(ft + ib * FD);
        float4* fdst = (float4*)(out_feats + ((long)img * DET + j * 25) * FD);
        const int* sp = &g_selp[img][j * 25];
        for (int i = tid; i < tot; i += NTHR) {
            int dr = i / FD4, col = i - dr * FD4;
            fdst[(long)dr * FD4 + col] = fsrc[(long)sp[dr] * FD4 + col];
        }
        for (int i = tid; i < DBINS / 4; i += NTHR)
            g_hist[img][j * (DBINS / 4) + i] = 0u;
        __threadfence();
        __syncthreads();
        if (tid == 0) {
            unsigned pos = atomicAdd(&g_edone[img], 1u);
            if (pos == 3u) {
                g_adone[img] = 0u;
                g_dflag[img] = 0u;
                g_edone[img] = 0u;
                __threadfence();
            }
        }
    }
}

extern "C" void kernel_launch(void* const* d_in, const int* in_sizes, int n_in,
                              void* d_out, int out_size) {
    const float* lg    = (const float*)d_in[0];
    const float* reg   = (const float*)d_in[1];
    const float* props = (const float*)d_in[2];
    const float* ft    = (const float*)d_in[3];
    int N  = in_sizes[0] / NC;     // 32768
    int P  = N / BIMG;             // 4096
    int FD = in_sizes[3] / N;      // 1024
    float* out_boxes = (float*)d_out;
    float* out_feats = out_boxes + (long)BIMG * DET * 4;

    fused_rcnn<<<NBLK, NTHR>>>(lg, reg, props, ft, out_boxes, out_feats, P, FD);
}